// round 15
// baseline (speedup 1.0000x reference)
#include <cuda_runtime.h>

// out[col] = depth[k1]/NORM, k1 = first k in [0,106] with a valid sign change.
//   signs s[k] = sgn(ssp[k+1]-ssp[k]), k=0..105
//   change: k==0 -> s[0]<0 ; 1<=k<=105 -> s[k]<s[k-1] ; k==106 -> s[105]>0
//   killed if [1,0,1] at (k-1,k,k+1) (k<=104) or [1,-1,0,0] at (k-1..k+2) (k<=103)
//   depth[0] contributes 0.

struct Scan { int h0, h1, h2, h3; int k; bool done; };

static __device__ __forceinline__ int sgn_cmp(float a, float b) {
    return (int)(b > a) - (int)(b < a);
}

static __device__ __forceinline__ int sbit(unsigned P, unsigned N, int i) {
    return (int)((P >> i) & 1u) - (int)((N >> i) & 1u);
}

// decides k = jj-2 (jj >= 3 only here)
static __device__ __forceinline__ void step_t(Scan& s, int sj, int jj) {
    s.h3 = s.h2; s.h2 = s.h1; s.h1 = s.h0; s.h0 = sj;
    if (!s.done) {
        bool change = s.h2 < s.h3;
        bool p1 = (s.h3 == 1) & (s.h2 == 0)  & (s.h1 == 1);
        bool p2 = (s.h3 == 1) & (s.h2 == -1) & (s.h1 == 0) & (s.h0 == 0);
        if (change & (!p1) & (!p2)) { s.done = true; s.k = jj - 2; }
    }
}

// Head: 13 slices -> signs 0..11 -> decide k in [0,9], or -1.
static __device__ __forceinline__ int head_decide(const float x[13], unsigned& P, unsigned& N) {
    unsigned p = 0, n = 0;
    #pragma unroll
    for (int i = 0; i < 12; ++i) {
        p |= ((unsigned)(x[i + 1] > x[i])) << i;
        n |= ((unsigned)(x[i + 1] < x[i])) << i;
    }
    P = p; N = n;
    unsigned Z  = ~(p | n) & 0xFFFu;
    unsigned C  = ((p << 1) & ~p) | ((Z << 1) & n);
    unsigned P1 = (p << 1) & Z & (p >> 1);
    unsigned P2 = (p << 1) & n & (Z >> 1) & (Z >> 2);
    unsigned vmask = ((C & ~(P1 | P2)) | (n & 1u)) & 0x3FFu;  // k = 0..9
    return vmask ? (__ffs(vmask) - 1) : -1;
}

// Tail: one batched round trip of 16 slices (signs 12..27, decide k=10..25),
// then (essentially never) serial chunks for k>=26.
// p = column base, x12 = x[12], hp/hn bits 0..3 = signs 8..11.
static __device__ __noinline__ int tail2(const float* __restrict__ p, float x12,
                                         unsigned hp, unsigned hn) {
    const int HW = 65536;
    float y[16];
    #pragma unroll
    for (int i = 0; i < 16; ++i) y[i] = __ldg(p + (13 + i) * HW);

    // local bit j = global sign (8 + j); bits 0..3 from history, 4..19 new
    unsigned pm = hp & 0xFu, nm = hn & 0xFu;
    float prev = x12;
    #pragma unroll
    for (int i = 0; i < 16; ++i) {
        pm |= ((unsigned)(y[i] > prev)) << (4 + i);
        nm |= ((unsigned)(y[i] < prev)) << (4 + i);
        prev = y[i];
    }
    unsigned Z  = ~(pm | nm) & 0xFFFFFu;
    unsigned C  = ((pm << 1) & ~pm) | ((Z << 1) & nm);
    unsigned P1 = (pm << 1) & Z & (pm >> 1);
    unsigned P2 = (pm << 1) & nm & (Z >> 1) & (Z >> 2);
    unsigned vm = (C & ~(P1 | P2)) & 0x3FFFCu;  // local bits 2..17 -> global k 10..25
    if (vm) return 8 + (__ffs(vm) - 1);

    // Serial fallback from sign 28 (x0 = y[15] = x[28], history s[24..27])
    Scan st;
    st.h3 = sbit(pm, nm, 16); st.h2 = sbit(pm, nm, 17);
    st.h1 = sbit(pm, nm, 18); st.h0 = sbit(pm, nm, 19);
    st.k = 0; st.done = false;
    float x0 = y[15];
    int j = 28;
    #pragma unroll 1
    for (int c = 0; c < 19; ++c) {   // signs 28..103, decisions k = 26..101
        float x1 = __ldg(p + (j + 1) * HW);
        float x2 = __ldg(p + (j + 2) * HW);
        float x3 = __ldg(p + (j + 3) * HW);
        float x4 = __ldg(p + (j + 4) * HW);
        step_t(st, sgn_cmp(x0, x1), j);
        step_t(st, sgn_cmp(x1, x2), j + 1);
        step_t(st, sgn_cmp(x2, x3), j + 2);
        step_t(st, sgn_cmp(x3, x4), j + 3);
        x0 = x4;
        j += 4;
        if (st.done) return st.k;
    }
    // x0 = x[104], history = s[100..103]
    float x105 = __ldg(p + 105 * HW);
    float x106 = __ldg(p + 106 * HW);
    step_t(st, sgn_cmp(x0, x105), 104);     // decides k=102
    step_t(st, sgn_cmp(x105, x106), 105);   // decides k=103
    if (!st.done) {
        bool chg104 = st.h1 < st.h2;                               // k=104 change
        bool p1_104 = (st.h2 == 1) & (st.h1 == 0) & (st.h0 == 1);
        if (chg104 & (!p1_104))  st.k = 104;
        else if (st.h0 < st.h1)  st.k = 105;
        else if (st.h0 > 0)      st.k = 106;
        else                     st.k = 0;
    }
    return st.k;
}

__global__ void __launch_bounds__(128) ecs_kernel(
    const float* __restrict__ ssp,
    const float* __restrict__ depth_arr,
    float* __restrict__ out)
{
    const int HW = 65536;  // 256*256
    int t = blockIdx.x * 128 + threadIdx.x;   // 0..131071, 4 columns/thread
    int col0 = t * 4;
    const float* p = ssp + (long)(col0 >> 16) * (107L * HW) + (col0 & (HW - 1));
    const float4* p4 = reinterpret_cast<const float4*>(p);

    // One batched round trip: 13 x LDG.128 (512B/warp each)
    float4 v[13];
    #pragma unroll
    for (int i = 0; i < 13; ++i) v[i] = __ldg(p4 + i * (HW / 4));

    int k[4];
    unsigned P[4], N[4];
    {
        float xx[13];
        #pragma unroll
        for (int i = 0; i < 13; ++i) xx[i] = v[i].x;
        k[0] = head_decide(xx, P[0], N[0]);
    }
    {
        float xx[13];
        #pragma unroll
        for (int i = 0; i < 13; ++i) xx[i] = v[i].y;
        k[1] = head_decide(xx, P[1], N[1]);
    }
    {
        float xx[13];
        #pragma unroll
        for (int i = 0; i < 13; ++i) xx[i] = v[i].z;
        k[2] = head_decide(xx, P[2], N[2]);
    }
    {
        float xx[13];
        #pragma unroll
        for (int i = 0; i < 13; ++i) xx[i] = v[i].w;
        k[3] = head_decide(xx, P[3], N[3]);
    }

    // Rare per-lane tails: all lanes' tail loads issue in the same divergent
    // region -> one extra batched round trip for the warp, not four serial ones.
    if (k[0] < 0) k[0] = tail2(p + 0, v[12].x, P[0] >> 8, N[0] >> 8);
    if (k[1] < 0) k[1] = tail2(p + 1, v[12].y, P[1] >> 8, N[1] >> 8);
    if (k[2] < 0) k[2] = tail2(p + 2, v[12].z, P[2] >> 8, N[2] >> 8);
    if (k[3] < 0) k[3] = tail2(p + 3, v[12].w, P[3] >> 8, N[3] >> 8);

    const float INV_NORM = 1.0f / 670.25141631f;
    float4 res;
    res.x = (k[0] > 0) ? __ldg(depth_arr + k[0]) * INV_NORM : 0.0f;
    res.y = (k[1] > 0) ? __ldg(depth_arr + k[1]) * INV_NORM : 0.0f;
    res.z = (k[2] > 0) ? __ldg(depth_arr + k[2]) * INV_NORM : 0.0f;
    res.w = (k[3] > 0) ? __ldg(depth_arr + k[3]) * INV_NORM : 0.0f;
    reinterpret_cast<float4*>(out)[t] = res;
}

extern "C" void kernel_launch(void* const* d_in, const int* in_sizes, int n_in,
                              void* d_out, int out_size) {
    const float* ssp   = (const float*)d_in[0];
    const float* depth = (const float*)d_in[1];
    float* out = (float*)d_out;
    // out_size = 524288; 4 columns/thread, 128 threads/block -> 1024 blocks
    int blocks = out_size / 512;
    ecs_kernel<<<blocks, 128>>>(ssp, depth, out);
}

// round 16
// speedup vs baseline: 1.0333x; 1.0333x over previous
#include <cuda_runtime.h>

// out[col] = depth[k1]/NORM, k1 = first k in [0,106] with a valid sign change.
//   signs s[k] = sgn(ssp[k+1]-ssp[k]), k=0..105
//   change: k==0 -> s[0]<0 ; 1<=k<=105 -> s[k]<s[k-1] ; k==106 -> s[105]>0
//   killed if [1,0,1] at (k-1,k,k+1) (k<=104) or [1,-1,0,0] at (k-1..k+2) (k<=103)
//   depth[0] contributes 0.

struct Scan { int h0, h1, h2, h3; int k; bool done; };

static __device__ __forceinline__ int sgn_cmp(float a, float b) {
    return (int)(b > a) - (int)(b < a);
}

static __device__ __forceinline__ int sbit(unsigned P, unsigned N, int i) {
    return (int)((P >> i) & 1u) - (int)((N >> i) & 1u);
}

// decides k = jj-2 (jj >= 3 only here)
static __device__ __forceinline__ void step_t(Scan& s, int sj, int jj) {
    s.h3 = s.h2; s.h2 = s.h1; s.h1 = s.h0; s.h0 = sj;
    if (!s.done) {
        bool change = s.h2 < s.h3;
        bool p1 = (s.h3 == 1) & (s.h2 == 0)  & (s.h1 == 1);
        bool p2 = (s.h3 == 1) & (s.h2 == -1) & (s.h1 == 0) & (s.h0 == 0);
        if (change & (!p1) & (!p2)) { s.done = true; s.k = jj - 2; }
    }
}

// Head: 13 slices -> signs 0..11 -> decide k in [0,9], or -1.
static __device__ __forceinline__ int head_decide(const float x[13], unsigned& P, unsigned& N) {
    unsigned p = 0, n = 0;
    #pragma unroll
    for (int i = 0; i < 12; ++i) {
        p |= ((unsigned)(x[i + 1] > x[i])) << i;
        n |= ((unsigned)(x[i + 1] < x[i])) << i;
    }
    P = p; N = n;
    unsigned Z  = ~(p | n) & 0xFFFu;
    unsigned C  = ((p << 1) & ~p) | ((Z << 1) & n);
    unsigned P1 = (p << 1) & Z & (p >> 1);
    unsigned P2 = (p << 1) & n & (Z >> 1) & (Z >> 2);
    unsigned vmask = ((C & ~(P1 | P2)) | (n & 1u)) & 0x3FFu;  // k = 0..9
    return vmask ? (__ffs(vmask) - 1) : -1;
}

// Tail: one batched round trip of 16 slices (signs 12..27, decide k=10..25),
// then (essentially never) serial chunks for k>=26.
// p = column base, x12 = x[12], hp/hn bits 0..3 = signs 8..11.
static __device__ __noinline__ int tail2(const float* __restrict__ p, float x12,
                                         unsigned hp, unsigned hn) {
    const int HW = 65536;
    float y[16];
    #pragma unroll
    for (int i = 0; i < 16; ++i) y[i] = __ldg(p + (13 + i) * HW);

    // local bit j = global sign (8 + j); bits 0..3 from history, 4..19 new
    unsigned pm = hp & 0xFu, nm = hn & 0xFu;
    float prev = x12;
    #pragma unroll
    for (int i = 0; i < 16; ++i) {
        pm |= ((unsigned)(y[i] > prev)) << (4 + i);
        nm |= ((unsigned)(y[i] < prev)) << (4 + i);
        prev = y[i];
    }
    unsigned Z  = ~(pm | nm) & 0xFFFFFu;
    unsigned C  = ((pm << 1) & ~pm) | ((Z << 1) & nm);
    unsigned P1 = (pm << 1) & Z & (pm >> 1);
    unsigned P2 = (pm << 1) & nm & (Z >> 1) & (Z >> 2);
    unsigned vm = (C & ~(P1 | P2)) & 0x3FFFCu;  // local bits 2..17 -> global k 10..25
    if (vm) return 8 + (__ffs(vm) - 1);

    // Serial fallback from sign 28 (x0 = y[15] = x[28], history s[24..27])
    Scan st;
    st.h3 = sbit(pm, nm, 16); st.h2 = sbit(pm, nm, 17);
    st.h1 = sbit(pm, nm, 18); st.h0 = sbit(pm, nm, 19);
    st.k = 0; st.done = false;
    float x0 = y[15];
    int j = 28;
    #pragma unroll 1
    for (int c = 0; c < 19; ++c) {   // signs 28..103, decisions k = 26..101
        float x1 = __ldg(p + (j + 1) * HW);
        float x2 = __ldg(p + (j + 2) * HW);
        float x3 = __ldg(p + (j + 3) * HW);
        float x4 = __ldg(p + (j + 4) * HW);
        step_t(st, sgn_cmp(x0, x1), j);
        step_t(st, sgn_cmp(x1, x2), j + 1);
        step_t(st, sgn_cmp(x2, x3), j + 2);
        step_t(st, sgn_cmp(x3, x4), j + 3);
        x0 = x4;
        j += 4;
        if (st.done) return st.k;
    }
    // x0 = x[104], history = s[100..103]
    float x105 = __ldg(p + 105 * HW);
    float x106 = __ldg(p + 106 * HW);
    step_t(st, sgn_cmp(x0, x105), 104);     // decides k=102
    step_t(st, sgn_cmp(x105, x106), 105);   // decides k=103
    if (!st.done) {
        bool chg104 = st.h1 < st.h2;                               // k=104 change
        bool p1_104 = (st.h2 == 1) & (st.h1 == 0) & (st.h0 == 1);
        if (chg104 & (!p1_104))  st.k = 104;
        else if (st.h0 < st.h1)  st.k = 105;
        else if (st.h0 > 0)      st.k = 106;
        else                     st.k = 0;
    }
    return st.k;
}

__global__ void __launch_bounds__(128) ecs_kernel(
    const float* __restrict__ ssp,
    const float* __restrict__ depth_arr,
    float* __restrict__ out)
{
    const int HW = 65536;  // 256*256
    int t = blockIdx.x * 128 + threadIdx.x;   // 0..131071, 4 columns/thread
    int col0 = t * 4;
    const float* p = ssp + (long)(col0 >> 16) * (107L * HW) + (col0 & (HW - 1));
    const float4* p4 = reinterpret_cast<const float4*>(p);

    // One batched round trip: 13 x LDG.128 (512B/warp each)
    float4 v[13];
    #pragma unroll
    for (int i = 0; i < 13; ++i) v[i] = __ldg(p4 + i * (HW / 4));

    int k[4];
    unsigned P[4], N[4];
    {
        float xx[13];
        #pragma unroll
        for (int i = 0; i < 13; ++i) xx[i] = v[i].x;
        k[0] = head_decide(xx, P[0], N[0]);
    }
    {
        float xx[13];
        #pragma unroll
        for (int i = 0; i < 13; ++i) xx[i] = v[i].y;
        k[1] = head_decide(xx, P[1], N[1]);
    }
    {
        float xx[13];
        #pragma unroll
        for (int i = 0; i < 13; ++i) xx[i] = v[i].z;
        k[2] = head_decide(xx, P[2], N[2]);
    }
    {
        float xx[13];
        #pragma unroll
        for (int i = 0; i < 13; ++i) xx[i] = v[i].w;
        k[3] = head_decide(xx, P[3], N[3]);
    }

    // Rare per-lane tails: all lanes' tail loads issue in the same divergent
    // region -> one extra batched round trip for the warp, not four serial ones.
    if (k[0] < 0) k[0] = tail2(p + 0, v[12].x, P[0] >> 8, N[0] >> 8);
    if (k[1] < 0) k[1] = tail2(p + 1, v[12].y, P[1] >> 8, N[1] >> 8);
    if (k[2] < 0) k[2] = tail2(p + 2, v[12].z, P[2] >> 8, N[2] >> 8);
    if (k[3] < 0) k[3] = tail2(p + 3, v[12].w, P[3] >> 8, N[3] >> 8);

    const float INV_NORM = 1.0f / 670.25141631f;
    float4 res;
    res.x = (k[0] > 0) ? __ldg(depth_arr + k[0]) * INV_NORM : 0.0f;
    res.y = (k[1] > 0) ? __ldg(depth_arr + k[1]) * INV_NORM : 0.0f;
    res.z = (k[2] > 0) ? __ldg(depth_arr + k[2]) * INV_NORM : 0.0f;
    res.w = (k[3] > 0) ? __ldg(depth_arr + k[3]) * INV_NORM : 0.0f;
    reinterpret_cast<float4*>(out)[t] = res;
}

extern "C" void kernel_launch(void* const* d_in, const int* in_sizes, int n_in,
                              void* d_out, int out_size) {
    const float* ssp   = (const float*)d_in[0];
    const float* depth = (const float*)d_in[1];
    float* out = (float*)d_out;
    // out_size = 524288; 4 columns/thread, 128 threads/block -> 1024 blocks
    int blocks = out_size / 512;
    ecs_kernel<<<blocks, 128>>>(ssp, depth, out);
}